// round 2
// baseline (speedup 1.0000x reference)
#include <cuda_runtime.h>
#include <cuda_fp16.h>
#include <cstdint>

#define K_DIM 4096
#define N_DIM 4096
#define M_DIM 8192

#define BM 128
#define BN 128
#define BK 32
#define PADH 8
#define NTILES (K_DIM / BK)

// Dequantized weights, [N][K] with K contiguous (acts as col-major B for row.col MMA).
__device__ __half g_W[(size_t)N_DIM * K_DIM];
// x converted fp32 -> fp16 (exact: values originated as fp16).
__device__ __half g_X[(size_t)M_DIM * K_DIM];

// ---------------------------------------------------------------------------
// Kernel 0: convert x (float32 from harness) to fp16 scratch.
// ---------------------------------------------------------------------------
__global__ __launch_bounds__(256) void convert_x_kernel(const float* __restrict__ xf) {
    size_t i = ((size_t)blockIdx.x * blockDim.x + threadIdx.x) * 8;
    float4 v0 = *reinterpret_cast<const float4*>(xf + i);
    float4 v1 = *reinterpret_cast<const float4*>(xf + i + 4);
    __half h[8];
    h[0] = __float2half_rn(v0.x); h[1] = __float2half_rn(v0.y);
    h[2] = __float2half_rn(v0.z); h[3] = __float2half_rn(v0.w);
    h[4] = __float2half_rn(v1.x); h[5] = __float2half_rn(v1.y);
    h[6] = __float2half_rn(v1.z); h[7] = __float2half_rn(v1.w);
    *reinterpret_cast<uint4*>(&g_X[i]) = *reinterpret_cast<const uint4*>(h);
}

// ---------------------------------------------------------------------------
// Kernel 1: GPTQ 4-bit dequant.  qweight[r][n] packs k = r*8..r*8+7 (4 bits each).
// qzeros[g][c] packs n = c*8..c*8+7.  group g = k/128 = r/16 (constant across the
// 8 k's in one word).  w = fp16(wi - (z+1)) * fp16(scale), fp16 multiply to match
// the reference's rounding.  scales arrive as float32 (exact fp16 values).
// ---------------------------------------------------------------------------
__global__ __launch_bounds__(256) void dequant_kernel(const int* __restrict__ qw,
                                                      const float* __restrict__ scales,
                                                      const int* __restrict__ qz) {
    int idx = blockIdx.x * blockDim.x + threadIdx.x;
    int r = idx & 511;          // K_DIM/8 = 512 rows of qweight
    int n = idx >> 9;
    int w = qw[r * N_DIM + n];
    int g = r >> 4;             // (r*8)/128
    int zw = qz[g * (N_DIM / 8) + (n >> 3)];
    int z = ((zw >> ((n & 7) * 4)) & 0xF) + 1;
    __half s = __float2half_rn(scales[g * N_DIM + n]);
    __half vals[8];
#pragma unroll
    for (int j = 0; j < 8; j++) {
        int wi = ((w >> (4 * j)) & 0xF) - z;
        vals[j] = __hmul(__int2half_rn(wi), s);
    }
    // consecutive threads -> consecutive r -> contiguous 16B stores within row n
    *reinterpret_cast<uint4*>(&g_W[(size_t)n * K_DIM + r * 8]) =
        *reinterpret_cast<const uint4*>(vals);
}

// ---------------------------------------------------------------------------
// Kernel 2: fp16 GEMM, fp32 accum.  out[m][n] = sum_k x[m][k]*W[n][k] + bias[n]
// 128x128x32 CTA tile, 8 warps as 2(M)x4(N), warp tile 64x32 = 4x4 m16n8k16.
// 2-stage cp.async pipeline; ldmatrix (no trans) from padded smem.
// Output float32; bias float32 (exact fp16 values) -> rounded to fp16 math.
// ---------------------------------------------------------------------------
__global__ __launch_bounds__(256) void gemm_kernel(const float* __restrict__ biasf,
                                                   float* __restrict__ out) {
    __shared__ __half As[2][BM][BK + PADH];
    __shared__ __half Bs[2][BN][BK + PADH];

    const int tid = threadIdx.x;
    const int lane = tid & 31;
    const int warp = tid >> 5;
    const int warpM = warp & 1;   // 0..1
    const int warpN = warp >> 1;  // 0..3
    const int bm = blockIdx.y * BM;
    const int bn = blockIdx.x * BN;

    float c[4][4][4];
#pragma unroll
    for (int i = 0; i < 4; i++)
#pragma unroll
        for (int j = 0; j < 4; j++)
#pragma unroll
            for (int e = 0; e < 4; e++) c[i][j][e] = 0.0f;

    auto load_stage = [&](int s, int kt) {
#pragma unroll
        for (int i = 0; i < 2; i++) {
            int id = tid + i * 256;      // 512 16B vectors per operand per stage
            int row = id >> 2;           // 0..127
            int c8 = (id & 3) * 8;       // 0,8,16,24 halves
            const __half* srcA = g_X + (size_t)(bm + row) * K_DIM + kt * BK + c8;
            uint32_t dA = (uint32_t)__cvta_generic_to_shared(&As[s][row][c8]);
            asm volatile("cp.async.cg.shared.global [%0], [%1], 16;" :: "r"(dA), "l"(srcA));
            const __half* srcB = g_W + (size_t)(bn + row) * K_DIM + kt * BK + c8;
            uint32_t dB = (uint32_t)__cvta_generic_to_shared(&Bs[s][row][c8]);
            asm volatile("cp.async.cg.shared.global [%0], [%1], 16;" :: "r"(dB), "l"(srcB));
        }
        asm volatile("cp.async.commit_group;");
    };

    load_stage(0, 0);
    int cur = 0;

    for (int kt = 0; kt < NTILES; kt++) {
        asm volatile("cp.async.wait_group 0;");
        __syncthreads();
        if (kt + 1 < NTILES) load_stage(cur ^ 1, kt + 1);

#pragma unroll
        for (int kk = 0; kk < BK; kk += 16) {
            uint32_t a[4][4];
#pragma unroll
            for (int fm = 0; fm < 4; fm++) {
                int m0 = warpM * 64 + fm * 16 + (lane & 15);
                uint32_t addr = (uint32_t)__cvta_generic_to_shared(
                    &As[cur][m0][kk + ((lane >> 4) << 3)]);
                asm volatile("ldmatrix.sync.aligned.m8n8.x4.shared.b16 {%0,%1,%2,%3}, [%4];"
                             : "=r"(a[fm][0]), "=r"(a[fm][1]), "=r"(a[fm][2]), "=r"(a[fm][3])
                             : "r"(addr));
            }
            uint32_t b[4][2];
#pragma unroll
            for (int fn = 0; fn < 4; fn++) {
                int n0 = warpN * 32 + fn * 8 + (lane & 7);
                uint32_t addr = (uint32_t)__cvta_generic_to_shared(
                    &Bs[cur][n0][kk + ((lane >> 3) & 1) * 8]);
                asm volatile("ldmatrix.sync.aligned.m8n8.x2.shared.b16 {%0,%1}, [%2];"
                             : "=r"(b[fn][0]), "=r"(b[fn][1])
                             : "r"(addr));
            }
#pragma unroll
            for (int fm = 0; fm < 4; fm++)
#pragma unroll
                for (int fn = 0; fn < 4; fn++) {
                    asm volatile(
                        "mma.sync.aligned.m16n8k16.row.col.f32.f16.f16.f32 "
                        "{%0,%1,%2,%3}, {%4,%5,%6,%7}, {%8,%9}, {%0,%1,%2,%3};"
                        : "+f"(c[fm][fn][0]), "+f"(c[fm][fn][1]),
                          "+f"(c[fm][fn][2]), "+f"(c[fm][fn][3])
                        : "r"(a[fm][0]), "r"(a[fm][1]), "r"(a[fm][2]), "r"(a[fm][3]),
                          "r"(b[fn][0]), "r"(b[fn][1]));
                }
        }
        cur ^= 1;
    }

    // Epilogue: mimic reference rounding: fp16(sum) + fp16(bias) in fp16, store f32.
    const int row_in = lane >> 2;         // 0..7
    const int col_in = (lane & 3) * 2;    // 0,2,4,6
#pragma unroll
    for (int fn = 0; fn < 4; fn++) {
        int n = bn + warpN * 32 + fn * 8 + col_in;
        __half bh0 = __float2half_rn(biasf[n]);
        __half bh1 = __float2half_rn(biasf[n + 1]);
#pragma unroll
        for (int fm = 0; fm < 4; fm++) {
            int m = bm + warpM * 64 + fm * 16 + row_in;
            float2 v0, v1;
            v0.x = __half2float(__hadd(__float2half_rn(c[fm][fn][0]), bh0));
            v0.y = __half2float(__hadd(__float2half_rn(c[fm][fn][1]), bh1));
            v1.x = __half2float(__hadd(__float2half_rn(c[fm][fn][2]), bh0));
            v1.y = __half2float(__hadd(__float2half_rn(c[fm][fn][3]), bh1));
            *reinterpret_cast<float2*>(&out[(size_t)m * N_DIM + n]) = v0;
            *reinterpret_cast<float2*>(&out[(size_t)(m + 8) * N_DIM + n]) = v1;
        }
    }
}

extern "C" void kernel_launch(void* const* d_in, const int* in_sizes, int n_in,
                              void* d_out, int out_size) {
    const float* x       = (const float*)d_in[0];
    const int*   qweight = (const int*)d_in[1];
    const float* scales  = (const float*)d_in[2];
    const int*   qzeros  = (const int*)d_in[3];
    // d_in[4] = g_idx: always k/128 for this problem -> folded into dequant indexing
    const float* bias    = (const float*)d_in[5];
    float* out = (float*)d_out;

    convert_x_kernel<<<((size_t)M_DIM * K_DIM) / (256 * 8), 256>>>(x);
    dequant_kernel<<<(512 * N_DIM) / 256, 256>>>(qweight, scales, qzeros);

    dim3 grid(N_DIM / BN, M_DIM / BM);
    gemm_kernel<<<grid, 256>>>(bias, out);
}